// round 5
// baseline (speedup 1.0000x reference)
#include <cuda_runtime.h>
#include <cuda_bf16.h>

#define NMAX 100000
#define EMAX 3400000
#define F 128
#define F4 32   // floats4 per row

// ---------------- scratch (module-load allocation, allowed) ----------------
__device__ int   g_outc[NMAX];
__device__ int   g_inc[NMAX];
__device__ int   g_fill[NMAX];
__device__ float g_outnorm[NMAX];
__device__ float g_innorm[NMAX];
__device__ int   g_rowptr[NMAX + 1];
__device__ int   g_blksum[1024];
__device__ int   g_colidx[EMAX];
__device__ float g_y[NMAX * F];    // scaled features (gather source)
__device__ float g_agg[NMAX * F];  // aggregated (in_norm applied)
__device__ float g_h[NMAX * F];    // hidden

// ---------------- graph preprocessing ----------------
__global__ void k_zero(int n) {
    int i = blockIdx.x * blockDim.x + threadIdx.x;
    if (i < n) { g_outc[i] = 0; g_inc[i] = 0; g_fill[i] = 0; }
}

__global__ void k_count(const int* __restrict__ src, const int* __restrict__ dst, int e) {
    int i = blockIdx.x * blockDim.x + threadIdx.x;
    if (i < e) {
        atomicAdd(&g_outc[src[i]], 1);
        atomicAdd(&g_inc[dst[i]], 1);
    }
}

// exclusive scan of g_inc -> g_rowptr (3-kernel: block scans, scan of block sums, add)
__global__ void k_scanA(int n) {
    __shared__ int s[256];
    int tid = threadIdx.x;
    int i = blockIdx.x * 256 + tid;
    int v = (i < n) ? g_inc[i] : 0;
    s[tid] = v;
    __syncthreads();
    #pragma unroll
    for (int off = 1; off < 256; off <<= 1) {
        int t = (tid >= off) ? s[tid - off] : 0;
        __syncthreads();
        s[tid] += t;
        __syncthreads();
    }
    if (i < n) g_rowptr[i] = s[tid] - v;            // exclusive within block
    if (tid == 255) g_blksum[blockIdx.x] = s[255];  // block total
}

__global__ void k_scanB(int nb) {
    __shared__ int s[512];
    int tid = threadIdx.x;
    int v = (tid < nb) ? g_blksum[tid] : 0;
    s[tid] = v;
    __syncthreads();
    #pragma unroll
    for (int off = 1; off < 512; off <<= 1) {
        int t = (tid >= off) ? s[tid - off] : 0;
        __syncthreads();
        s[tid] += t;
        __syncthreads();
    }
    if (tid < nb) g_blksum[tid] = s[tid] - v;       // exclusive block offsets
}

__global__ void k_scanC(int n, int e) {
    int i = blockIdx.x * 256 + threadIdx.x;
    if (i < n) g_rowptr[i] += g_blksum[blockIdx.x];
    if (i == 0) g_rowptr[n] = e;
}

__global__ void k_norms(int n) {
    int i = blockIdx.x * blockDim.x + threadIdx.x;
    if (i < n) {
        float od = (float)max(g_outc[i], 1);
        float id = (float)max(g_inc[i], 1);
        g_outnorm[i] = 1.0f / sqrtf(od);
        g_innorm[i]  = 1.0f / sqrtf(id);
    }
}

__global__ void k_fill(const int* __restrict__ src, const int* __restrict__ dst, int e) {
    int i = blockIdx.x * blockDim.x + threadIdx.x;
    if (i < e) {
        int d = dst[i];
        int p = g_rowptr[d] + atomicAdd(&g_fill[d], 1);
        g_colidx[p] = src[i];
    }
}

// ---------------- feature kernels ----------------
// y[r] = in[r] * out_norm[r]
__global__ void k_scale(const float* __restrict__ in, int n) {
    int i = blockIdx.x * blockDim.x + threadIdx.x;
    if (i < n * F4) {
        float4 v = reinterpret_cast<const float4*>(in)[i];
        float sc = g_outnorm[i >> 5];
        v.x *= sc; v.y *= sc; v.z *= sc; v.w *= sc;
        reinterpret_cast<float4*>(g_y)[i] = v;
    }
}

// agg[r] = in_norm[r] * sum_{e in CSR(r)} y[colidx[e]]
// one warp per dst row, 4 floats/lane, unroll-4 edge batches for MLP.
__global__ __launch_bounds__(256) void k_spmm(int n) {
    int w = (blockIdx.x * blockDim.x + threadIdx.x) >> 5;
    int lane = threadIdx.x & 31;
    if (w >= n) return;
    int s = g_rowptr[w];
    int e = g_rowptr[w + 1];
    const float4* __restrict__ y4 = reinterpret_cast<const float4*>(g_y);
    float ax = 0.f, ay = 0.f, az = 0.f, aw = 0.f;
    int i = s;
    for (; i + 4 <= e; i += 4) {
        int c0 = g_colidx[i], c1 = g_colidx[i + 1], c2 = g_colidx[i + 2], c3 = g_colidx[i + 3];
        float4 v0 = y4[c0 * F4 + lane];
        float4 v1 = y4[c1 * F4 + lane];
        float4 v2 = y4[c2 * F4 + lane];
        float4 v3 = y4[c3 * F4 + lane];
        ax += (v0.x + v1.x) + (v2.x + v3.x);
        ay += (v0.y + v1.y) + (v2.y + v3.y);
        az += (v0.z + v1.z) + (v2.z + v3.z);
        aw += (v0.w + v1.w) + (v2.w + v3.w);
    }
    for (; i < e; i++) {
        int c = g_colidx[i];
        float4 v = y4[c * F4 + lane];
        ax += v.x; ay += v.y; az += v.z; aw += v.w;
    }
    float sc = g_innorm[w];
    float4 r; r.x = ax * sc; r.y = ay * sc; r.z = az * sc; r.w = aw * sc;
    reinterpret_cast<float4*>(g_agg)[w * F4 + lane] = r;
}

// ---------------- register-tiled SGEMM: C[M,BN] = act(A[M,128] @ W[128,BN] + b) ----
// BM=128, BK=16, 256 threads (16x16), micro-tile 8 x TN.
// ACT: 0 none, 1 relu, 2 sigmoid
template <int BN, int TN, int ACT>
__global__ __launch_bounds__(256) void k_gemm(const float* __restrict__ A,
                                              const float* __restrict__ W,
                                              const float* __restrict__ bias,
                                              float* __restrict__ C, int M) {
    const int BM = 128, BK = 16, K = 128;
    __shared__ float As[BK][BM + 4];   // +4 pad keeps float4 reads 16B-aligned (528B row)
    __shared__ float Bs[BK][BN];
    int tid = threadIdx.x;
    int tx = tid & 15;          // 0..15 -> col group
    int ty = tid >> 4;          // 0..15 -> row group
    int rowBase = blockIdx.x * BM;

    float acc[8][TN];
    #pragma unroll
    for (int i = 0; i < 8; i++)
        #pragma unroll
        for (int j = 0; j < TN; j++) acc[i][j] = 0.f;

    for (int k0 = 0; k0 < K; k0 += BK) {
        // A tile: 128x16 -> As[k][m] (transposed store)
        #pragma unroll
        for (int i = tid; i < BM * BK / 4; i += 256) {
            int r = i >> 2;           // 0..127
            int c4 = i & 3;           // which float4 along k
            float4 v;
            if (rowBase + r < M)
                v = *reinterpret_cast<const float4*>(&A[(size_t)(rowBase + r) * K + k0 + c4 * 4]);
            else
                v = make_float4(0.f, 0.f, 0.f, 0.f);
            As[c4 * 4 + 0][r] = v.x;
            As[c4 * 4 + 1][r] = v.y;
            As[c4 * 4 + 2][r] = v.z;
            As[c4 * 4 + 3][r] = v.w;
        }
        // B tile: 16xBN
        #pragma unroll
        for (int i = tid; i < BK * BN / 4; i += 256) {
            int r = i / (BN / 4);
            int c4 = i % (BN / 4);
            *reinterpret_cast<float4*>(&Bs[r][c4 * 4]) =
                *reinterpret_cast<const float4*>(&W[(size_t)(k0 + r) * BN + c4 * 4]);
        }
        __syncthreads();

        #pragma unroll
        for (int kk = 0; kk < BK; kk++) {
            float a[8], b[TN];
            *reinterpret_cast<float4*>(&a[0]) = *reinterpret_cast<float4*>(&As[kk][ty * 8]);
            *reinterpret_cast<float4*>(&a[4]) = *reinterpret_cast<float4*>(&As[kk][ty * 8 + 4]);
            #pragma unroll
            for (int j = 0; j < TN; j += 4)
                *reinterpret_cast<float4*>(&b[j]) = *reinterpret_cast<float4*>(&Bs[kk][tx * TN + j]);
            #pragma unroll
            for (int i = 0; i < 8; i++)
                #pragma unroll
                for (int j = 0; j < TN; j++)
                    acc[i][j] = fmaf(a[i], b[j], acc[i][j]);
        }
        __syncthreads();
    }

    float bv[TN];
    #pragma unroll
    for (int j = 0; j < TN; j++) bv[j] = bias[tx * TN + j];

    #pragma unroll
    for (int i = 0; i < 8; i++) {
        int r = rowBase + ty * 8 + i;
        if (r < M) {
            #pragma unroll
            for (int j4 = 0; j4 < TN; j4 += 4) {
                float4 o;
                float* op = &o.x;
                #pragma unroll
                for (int j = 0; j < 4; j++) {
                    float v = acc[i][j4 + j] + bv[j4 + j];
                    if (ACT == 1) v = fmaxf(v, 0.f);
                    else if (ACT == 2) v = 1.f / (1.f + __expf(-v));
                    op[j] = v;
                }
                *reinterpret_cast<float4*>(&C[(size_t)r * BN + tx * TN + j4]) = o;
            }
        }
    }
}

// ---------------- launch ----------------
extern "C" void kernel_launch(void* const* d_in, const int* in_sizes, int n_in,
                              void* d_out, int out_size) {
    const float* x   = (const float*)d_in[0];
    const int*   src = (const int*)d_in[1];
    const int*   dst = (const int*)d_in[2];
    const float* W1  = (const float*)d_in[3];
    const float* b1  = (const float*)d_in[4];
    const float* W2  = (const float*)d_in[5];
    const float* b2  = (const float*)d_in[6];
    const float* Wm1 = (const float*)d_in[7];
    const float* bm1 = (const float*)d_in[8];
    const float* Wm2 = (const float*)d_in[9];
    const float* bm2 = (const float*)d_in[10];
    float* out = (float*)d_out;

    int n = in_sizes[0] / F;     // 100000
    int e = in_sizes[1];         // 3200000

    void *p_y, *p_agg, *p_h;
    cudaGetSymbolAddress(&p_y, g_y);
    cudaGetSymbolAddress(&p_agg, g_agg);
    cudaGetSymbolAddress(&p_h, g_h);
    float* y   = (float*)p_y;
    float* agg = (float*)p_agg;
    float* h   = (float*)p_h;

    int nbN = (n + 255) / 256;
    int nbE = (e + 255) / 256;
    int nbW = (n * 32 + 255) / 256;   // warp-per-row grid
    int nbV = (n * F4 + 255) / 256;   // float4-per-thread grid
    int nbG = (n + 127) / 128;        // gemm row blocks

    // graph preprocessing (CSR by dst + norms) — reused by both convs
    k_zero<<<nbN, 256>>>(n);
    k_count<<<nbE, 256>>>(src, dst, e);
    k_scanA<<<nbN, 256>>>(n);
    k_scanB<<<1, 512>>>(nbN);
    k_scanC<<<nbN, 256>>>(n, e);
    k_norms<<<nbN, 256>>>(n);
    k_fill<<<nbE, 256>>>(src, dst, e);

    // conv1: h = relu( (in_norm * scatter(gather(x*out_norm))) @ W1 + b1 )
    k_scale<<<nbV, 256>>>(x, n);
    k_spmm<<<nbW, 256>>>(n);
    k_gemm<128, 8, 1><<<nbG, 256>>>(agg, W1, b1, h, n);

    // conv2: y(reused) = relu( ... @ W2 + b2 )
    k_scale<<<nbV, 256>>>(h, n);
    k_spmm<<<nbW, 256>>>(n);
    k_gemm<128, 8, 1><<<nbG, 256>>>(agg, W2, b2, y, n);   // y now holds h2

    // MLP head
    k_gemm<128, 8, 1><<<nbG, 256>>>(y, Wm1, bm1, h, n);   // h = relu(h2@Wm1+bm1)
    k_gemm<64, 4, 2><<<nbG, 256>>>(h, Wm2, bm2, out, n);  // out = sigmoid(h@Wm2+bm2)
}

// round 6
// speedup vs baseline: 1.9564x; 1.9564x over previous
#include <cuda_runtime.h>
#include <cuda_fp16.h>
#include <cuda_bf16.h>
#include <cstdint>

#define NMAX 100000
#define EMAX 3400000
#define F 128
#define F4 32

// ---------------- scratch (module-load allocation, allowed) ----------------
__device__ int   g_outc[NMAX];
__device__ int   g_inc[NMAX];
__device__ int   g_fill[NMAX];
__device__ float g_outnorm[NMAX];
__device__ float g_innorm[NMAX];
__device__ int   g_rowptr[NMAX + 1];
__device__ int   g_blksum[1024];
__device__ int   g_colidx[EMAX];
__device__ __align__(16) __half g_yh[NMAX * F];    // fp16 features (gather source / gemm A)
__device__ __align__(16) __half g_aggh[NMAX * F];  // fp16 aggregated / gemm A
__device__ __align__(16) __half g_w1h[F * F];
__device__ __align__(16) __half g_w2h[F * F];
__device__ __align__(16) __half g_wm1h[F * F];
__device__ __align__(16) __half g_wm2h[F * 64];

// ---------------- graph preprocessing ----------------
__global__ void k_zero(int n) {
    int i = blockIdx.x * blockDim.x + threadIdx.x;
    if (i < n) { g_outc[i] = 0; g_inc[i] = 0; }
}

__global__ void k_count(const int* __restrict__ src, const int* __restrict__ dst, int e) {
    int i = blockIdx.x * blockDim.x + threadIdx.x;
    if (i < e) {
        atomicAdd(&g_outc[src[i]], 1);
        atomicAdd(&g_inc[dst[i]], 1);
    }
}

__global__ void k_scanA(int n) {
    __shared__ int s[256];
    int tid = threadIdx.x;
    int i = blockIdx.x * 256 + tid;
    int v = (i < n) ? g_inc[i] : 0;
    s[tid] = v;
    __syncthreads();
    #pragma unroll
    for (int off = 1; off < 256; off <<= 1) {
        int t = (tid >= off) ? s[tid - off] : 0;
        __syncthreads();
        s[tid] += t;
        __syncthreads();
    }
    if (i < n) g_rowptr[i] = s[tid] - v;
    if (tid == 255) g_blksum[blockIdx.x] = s[255];
}

__global__ void k_scanB(int nb) {
    __shared__ int s[512];
    int tid = threadIdx.x;
    int v = (tid < nb) ? g_blksum[tid] : 0;
    s[tid] = v;
    __syncthreads();
    #pragma unroll
    for (int off = 1; off < 512; off <<= 1) {
        int t = (tid >= off) ? s[tid - off] : 0;
        __syncthreads();
        s[tid] += t;
        __syncthreads();
    }
    if (tid < nb) g_blksum[tid] = s[tid] - v;
}

__global__ void k_scanC(int n, int e) {
    int i = blockIdx.x * 256 + threadIdx.x;
    if (i < n) {
        int v = g_rowptr[i] + g_blksum[blockIdx.x];
        g_rowptr[i] = v;
        g_fill[i] = v;          // fill cursor starts at row offset (saves a load in k_fill)
    }
    if (i == 0) g_rowptr[n] = e;
}

__global__ void k_norms(int n) {
    int i = blockIdx.x * blockDim.x + threadIdx.x;
    if (i < n) {
        float od = (float)max(g_outc[i], 1);
        float id = (float)max(g_inc[i], 1);
        g_outnorm[i] = 1.0f / sqrtf(od);
        g_innorm[i]  = 1.0f / sqrtf(id);
    }
}

__global__ void k_fill(const int* __restrict__ src, const int* __restrict__ dst, int e) {
    int i = blockIdx.x * blockDim.x + threadIdx.x;
    if (i < e) {
        int p = atomicAdd(&g_fill[dst[i]], 1);
        g_colidx[p] = src[i];
    }
}

// ---------------- fp32 -> fp16 weight convert ----------------
__global__ void k_f2h(const float* __restrict__ a, __half* __restrict__ o, int n) {
    int i = blockIdx.x * blockDim.x + threadIdx.x;
    if (i < n) o[i] = __float2half(a[i]);
}

// ---------------- x * out_norm -> fp16 y ----------------
__global__ void k_scale_h(const float* __restrict__ in, int n) {
    int i = blockIdx.x * blockDim.x + threadIdx.x;
    if (i < n * F4) {
        float4 v = reinterpret_cast<const float4*>(in)[i];
        float sc = g_outnorm[i >> 5];
        __half2 h0 = __floats2half2_rn(v.x * sc, v.y * sc);
        __half2 h1 = __floats2half2_rn(v.z * sc, v.w * sc);
        uint2 o;
        o.x = *reinterpret_cast<uint32_t*>(&h0);
        o.y = *reinterpret_cast<uint32_t*>(&h1);
        reinterpret_cast<uint2*>(g_yh)[i] = o;
    }
}

// ---------------- SpMM: aggh[r] = fp16( in_norm[r] * sum yh[colidx] ) ----------------
// one warp per dst row; lane owns 4 halves (8B); fp32 accumulation
__global__ __launch_bounds__(256) void k_spmm_h(int n) {
    int w = (blockIdx.x * blockDim.x + threadIdx.x) >> 5;
    int lane = threadIdx.x & 31;
    if (w >= n) return;
    int s = g_rowptr[w];
    int e = g_rowptr[w + 1];
    const uint2* __restrict__ yv = reinterpret_cast<const uint2*>(g_yh);
    float s0 = 0.f, s1 = 0.f, s2 = 0.f, s3 = 0.f;
    int i = s;
    for (; i + 4 <= e; i += 4) {
        int c0 = g_colidx[i], c1 = g_colidx[i + 1], c2 = g_colidx[i + 2], c3 = g_colidx[i + 3];
        uint2 u0 = yv[c0 * 32 + lane];
        uint2 u1 = yv[c1 * 32 + lane];
        uint2 u2 = yv[c2 * 32 + lane];
        uint2 u3 = yv[c3 * 32 + lane];
        #define ACCU(u) { \
            float2 f0 = __half22float2(*reinterpret_cast<__half2*>(&(u).x)); \
            float2 f1 = __half22float2(*reinterpret_cast<__half2*>(&(u).y)); \
            s0 += f0.x; s1 += f0.y; s2 += f1.x; s3 += f1.y; }
        ACCU(u0) ACCU(u1) ACCU(u2) ACCU(u3)
    }
    for (; i < e; i++) {
        uint2 u = yv[g_colidx[i] * 32 + lane];
        ACCU(u)
        #undef ACCU
    }
    float sc = g_innorm[w];
    __half2 h0 = __floats2half2_rn(s0 * sc, s1 * sc);
    __half2 h1 = __floats2half2_rn(s2 * sc, s3 * sc);
    uint2 o;
    o.x = *reinterpret_cast<uint32_t*>(&h0);
    o.y = *reinterpret_cast<uint32_t*>(&h1);
    reinterpret_cast<uint2*>(g_aggh)[w * 32 + lane] = o;
}

// ---------------- tensor-core GEMM: C = act(A[M,128] @ W[128,BN] + b) ----------------
// BM=128, full K=128 in smem (single stage), 8 warps (WM x WN), mma.m16n8k16 f16->f32.
// ACT: 1 relu, 2 sigmoid.  OUT: 0 fp16, 1 fp16*out_norm[row], 2 fp32.
template <int BN, int WM, int WN, int ACT, int OUT>
__global__ __launch_bounds__(256) void k_gemm_mma(const __half* __restrict__ A,
                                                  const __half* __restrict__ W,
                                                  const float* __restrict__ bias,
                                                  void* __restrict__ Cv, int M) {
    constexpr int LDA = 136;       // halves; 272B row stride (16B multiple)
    constexpr int LDB = BN + 8;
    constexpr int MT = 128 / (WM * 16);
    constexpr int NT = BN / (WN * 8);
    extern __shared__ __half sm[];
    __half* As = sm;
    __half* Bs = sm + 128 * LDA;

    int tid = threadIdx.x, lane = tid & 31, wid = tid >> 5;
    int warpM = wid % WM, warpN = wid / WM;
    int rowBase = blockIdx.x * 128;

    // A tile: 128 rows x 128 halves (16 uint4/row)
    #pragma unroll
    for (int idx = tid; idx < 2048; idx += 256) {
        int r = idx >> 4, c = idx & 15;
        uint4 v = make_uint4(0u, 0u, 0u, 0u);
        if (rowBase + r < M)
            v = *reinterpret_cast<const uint4*>(A + (size_t)(rowBase + r) * 128 + c * 8);
        *reinterpret_cast<uint4*>(As + r * LDA + c * 8) = v;
    }
    // B tile: 128 x BN
    constexpr int BV = 128 * (BN / 8);
    #pragma unroll
    for (int idx = tid; idx < BV; idx += 256) {
        int r = idx / (BN / 8), c = idx % (BN / 8);
        uint4 v = *reinterpret_cast<const uint4*>(W + (size_t)r * BN + c * 8);
        *reinterpret_cast<uint4*>(Bs + r * LDB + c * 8) = v;
    }
    __syncthreads();

    float acc[MT][NT][4];
    #pragma unroll
    for (int i = 0; i < MT; i++)
        #pragma unroll
        for (int j = 0; j < NT; j++)
            #pragma unroll
            for (int q = 0; q < 4; q++) acc[i][j][q] = 0.f;

    #pragma unroll
    for (int ks = 0; ks < 8; ks++) {
        int k0 = ks * 16;
        uint32_t af[MT][4], bf[NT][2];
        #pragma unroll
        for (int i = 0; i < MT; i++) {
            const __half* p = As + (warpM * MT * 16 + i * 16 + (lane & 15)) * LDA
                                 + k0 + ((lane >> 4) << 3);
            uint32_t sa = (uint32_t)__cvta_generic_to_shared(p);
            asm volatile("ldmatrix.sync.aligned.m8n8.x4.shared.b16 {%0,%1,%2,%3}, [%4];"
                         : "=r"(af[i][0]), "=r"(af[i][1]), "=r"(af[i][2]), "=r"(af[i][3])
                         : "r"(sa));
        }
        #pragma unroll
        for (int j = 0; j < NT; j++) {
            const __half* p = Bs + (k0 + (lane & 15)) * LDB + warpN * NT * 8 + j * 8;
            uint32_t sb = (uint32_t)__cvta_generic_to_shared(p);
            asm volatile("ldmatrix.sync.aligned.m8n8.x2.trans.shared.b16 {%0,%1}, [%2];"
                         : "=r"(bf[j][0]), "=r"(bf[j][1]) : "r"(sb));
        }
        #pragma unroll
        for (int i = 0; i < MT; i++)
            #pragma unroll
            for (int j = 0; j < NT; j++) {
                asm volatile(
                    "mma.sync.aligned.m16n8k16.row.col.f32.f16.f16.f32 "
                    "{%0,%1,%2,%3}, {%4,%5,%6,%7}, {%8,%9}, {%0,%1,%2,%3};\n"
                    : "+f"(acc[i][j][0]), "+f"(acc[i][j][1]),
                      "+f"(acc[i][j][2]), "+f"(acc[i][j][3])
                    : "r"(af[i][0]), "r"(af[i][1]), "r"(af[i][2]), "r"(af[i][3]),
                      "r"(bf[j][0]), "r"(bf[j][1]));
            }
    }

    // epilogue
    int g = lane >> 2, t = lane & 3;
    #pragma unroll
    for (int i = 0; i < MT; i++) {
        int rr = rowBase + warpM * MT * 16 + i * 16 + g;
        #pragma unroll
        for (int j = 0; j < NT; j++) {
            int col = warpN * NT * 8 + j * 8 + 2 * t;
            float bv0 = bias[col], bv1 = bias[col + 1];
            #pragma unroll
            for (int half_m = 0; half_m < 2; half_m++) {
                int r = rr + half_m * 8;
                if (r >= M) continue;
                float v0 = acc[i][j][half_m * 2 + 0] + bv0;
                float v1 = acc[i][j][half_m * 2 + 1] + bv1;
                if (ACT == 1) { v0 = fmaxf(v0, 0.f); v1 = fmaxf(v1, 0.f); }
                else         { v0 = 1.f / (1.f + __expf(-v0)); v1 = 1.f / (1.f + __expf(-v1)); }
                if (OUT == 2) {
                    float2 o; o.x = v0; o.y = v1;
                    *reinterpret_cast<float2*>((float*)Cv + (size_t)r * BN + col) = o;
                } else {
                    if (OUT == 1) { float s = g_outnorm[r]; v0 *= s; v1 *= s; }
                    __half2 h = __floats2half2_rn(v0, v1);
                    *reinterpret_cast<__half2*>((__half*)Cv + (size_t)r * BN + col) = h;
                }
            }
        }
    }
}

// ---------------- launch ----------------
extern "C" void kernel_launch(void* const* d_in, const int* in_sizes, int n_in,
                              void* d_out, int out_size) {
    const float* x   = (const float*)d_in[0];
    const int*   src = (const int*)d_in[1];
    const int*   dst = (const int*)d_in[2];
    const float* W1  = (const float*)d_in[3];
    const float* b1  = (const float*)d_in[4];
    const float* W2  = (const float*)d_in[5];
    const float* b2  = (const float*)d_in[6];
    const float* Wm1 = (const float*)d_in[7];
    const float* bm1 = (const float*)d_in[8];
    const float* Wm2 = (const float*)d_in[9];
    const float* bm2 = (const float*)d_in[10];
    float* out = (float*)d_out;

    int n = in_sizes[0] / F;     // 100000
    int e = in_sizes[1];         // 3200000

    void *p_yh, *p_aggh, *p_w1h, *p_w2h, *p_wm1h, *p_wm2h;
    cudaGetSymbolAddress(&p_yh, g_yh);
    cudaGetSymbolAddress(&p_aggh, g_aggh);
    cudaGetSymbolAddress(&p_w1h, g_w1h);
    cudaGetSymbolAddress(&p_w2h, g_w2h);
    cudaGetSymbolAddress(&p_wm1h, g_wm1h);
    cudaGetSymbolAddress(&p_wm2h, g_wm2h);
    __half* yh   = (__half*)p_yh;
    __half* aggh = (__half*)p_aggh;
    __half* w1h  = (__half*)p_w1h;
    __half* w2h  = (__half*)p_w2h;
    __half* wm1h = (__half*)p_wm1h;
    __half* wm2h = (__half*)p_wm2h;

    const int SMEM128 = (128 * 136 + 128 * 136) * 2;   // 69632
    const int SMEM64  = (128 * 136 + 128 * 72) * 2;    // 53248
    cudaFuncSetAttribute(k_gemm_mma<128, 2, 4, 1, 1>,
                         cudaFuncAttributeMaxDynamicSharedMemorySize, SMEM128);
    cudaFuncSetAttribute(k_gemm_mma<128, 2, 4, 1, 0>,
                         cudaFuncAttributeMaxDynamicSharedMemorySize, SMEM128);
    cudaFuncSetAttribute(k_gemm_mma<64, 4, 2, 2, 2>,
                         cudaFuncAttributeMaxDynamicSharedMemorySize, SMEM64);

    int nbN = (n + 255) / 256;
    int nbE = (e + 255) / 256;
    int nbW = (n * 32 + 255) / 256;
    int nbV = (n * F4 + 255) / 256;
    int nbG = (n + 127) / 128;

    // graph preprocessing (CSR by dst + norms)
    k_zero<<<nbN, 256>>>(n);
    k_count<<<nbE, 256>>>(src, dst, e);
    k_scanA<<<nbN, 256>>>(n);
    k_scanB<<<1, 512>>>(nbN);
    k_scanC<<<nbN, 256>>>(n, e);
    k_norms<<<nbN, 256>>>(n);
    k_fill<<<nbE, 256>>>(src, dst, e);

    // weights -> fp16
    k_f2h<<<(F * F + 255) / 256, 256>>>(W1, w1h, F * F);
    k_f2h<<<(F * F + 255) / 256, 256>>>(W2, w2h, F * F);
    k_f2h<<<(F * F + 255) / 256, 256>>>(Wm1, wm1h, F * F);
    k_f2h<<<(F * 64 + 255) / 256, 256>>>(Wm2, wm2h, F * 64);

    // conv1
    k_scale_h<<<nbV, 256>>>(x, n);                                   // yh = fp16(x * out_norm)
    k_spmm_h<<<nbW, 256>>>(n);                                       // aggh = fp16(in_norm * S yh)
    k_gemm_mma<128, 2, 4, 1, 1><<<nbG, 256, SMEM128>>>(aggh, w1h, b1, (void*)yh, n);
                                                                     // yh = fp16(relu(.)@W1 * out_norm)
    // conv2
    k_spmm_h<<<nbW, 256>>>(n);                                       // aggh = fp16(in_norm * S yh)
    k_gemm_mma<128, 2, 4, 1, 0><<<nbG, 256, SMEM128>>>(aggh, w2h, b2, (void*)yh, n);
                                                                     // yh = fp16(relu h2)
    // MLP head
    k_gemm_mma<128, 2, 4, 1, 0><<<nbG, 256, SMEM128>>>(yh, wm1h, bm1, (void*)aggh, n);
                                                                     // aggh = fp16(relu m1)
    k_gemm_mma<64, 4, 2, 2, 2><<<nbG, 256, SMEM64>>>(aggh, wm2h, bm2, (void*)out, n);
                                                                     // out = sigmoid(.)  fp32
}

// round 12
// speedup vs baseline: 2.0196x; 1.0323x over previous
#include <cuda_runtime.h>
#include <cuda_fp16.h>
#include <cuda_bf16.h>
#include <cstdint>

#define NMAX 100000
#define EMAX 3400000
#define F 128
#define F4 32

// ---------------- scratch (module-load allocation, allowed) ----------------
__device__ int   g_outc[NMAX];
__device__ int   g_inc[NMAX];
__device__ int   g_fill[NMAX];
__device__ float g_outnorm[NMAX];
__device__ float g_innorm[NMAX];
__device__ int   g_rowptr[NMAX];
__device__ int   g_rowend[NMAX];
__device__ int   g_cursor;
__device__ int   g_colidx[EMAX];
__device__ __align__(16) __half g_yh[NMAX * F];    // fp16 features (gather source / gemm A)
__device__ __align__(16) __half g_aggh[NMAX * F];  // fp16 aggregated (gemm A)
__device__ __align__(16) __half g_w1h[F * F];
__device__ __align__(16) __half g_w2h[F * F];
__device__ __align__(16) __half g_wm1h[F * F];
__device__ __align__(16) __half g_wm2h[F * 64];

// ---------------- graph preprocessing ----------------
__global__ void k_zero(int n) {
    int i = blockIdx.x * blockDim.x + threadIdx.x;
    if (i < n) { g_outc[i] = 0; g_inc[i] = 0; }
    if (i == 0) g_cursor = 0;
}

__global__ void k_count(const int* __restrict__ src, const int* __restrict__ dst, int e) {
    int i = blockIdx.x * blockDim.x + threadIdx.x;
    if (i < e) {
        atomicAdd(&g_outc[src[i]], 1);
        atomicAdd(&g_inc[dst[i]], 1);
    }
}

// fused: block scan of in-degrees + atomic base alloc + norms.
// Row segments land in block-arrival order (any partition of [0,e) is a valid CSR).
__global__ void k_scan_norm(int n) {
    __shared__ int s[256];
    __shared__ int base;
    int tid = threadIdx.x;
    int i = blockIdx.x * 256 + tid;
    int deg = (i < n) ? g_inc[i] : 0;
    s[tid] = deg;
    __syncthreads();
    #pragma unroll
    for (int off = 1; off < 256; off <<= 1) {
        int t = (tid >= off) ? s[tid - off] : 0;
        __syncthreads();
        s[tid] += t;
        __syncthreads();
    }
    if (tid == 255) base = atomicAdd(&g_cursor, s[255]);
    __syncthreads();
    if (i < n) {
        int p = base + s[tid] - deg;
        g_rowptr[i] = p;
        g_rowend[i] = p + deg;
        g_fill[i]   = p;
        float od = (float)max(g_outc[i], 1);
        float id = (float)max(deg, 1);
        g_outnorm[i] = 1.0f / sqrtf(od);
        g_innorm[i]  = 1.0f / sqrtf(id);
    }
}

__global__ void k_fill(const int* __restrict__ src, const int* __restrict__ dst, int e) {
    int i = blockIdx.x * blockDim.x + threadIdx.x;
    if (i < e) {
        int p = atomicAdd(&g_fill[dst[i]], 1);
        g_colidx[p] = src[i];
    }
}

// ---------------- all weights fp32 -> fp16 in one launch ----------------
__global__ void k_f2h_all(const float* __restrict__ a0, const float* __restrict__ a1,
                          const float* __restrict__ a2, const float* __restrict__ a3) {
    int i = blockIdx.x * blockDim.x + threadIdx.x;   // 0 .. 57343
    if (i < 16384)           g_w1h[i]          = __float2half(a0[i]);
    else if (i < 32768)      g_w2h[i - 16384]  = __float2half(a1[i - 16384]);
    else if (i < 49152)      g_wm1h[i - 32768] = __float2half(a2[i - 32768]);
    else if (i < 57344)      g_wm2h[i - 49152] = __float2half(a3[i - 49152]);
}

// ---------------- x * out_norm -> fp16 y ----------------
__global__ void k_scale_h(const float* __restrict__ in, int n) {
    int i = blockIdx.x * blockDim.x + threadIdx.x;
    if (i < n * F4) {
        float4 v = reinterpret_cast<const float4*>(in)[i];
        float sc = g_outnorm[i >> 5];
        __half2 h0 = __floats2half2_rn(v.x * sc, v.y * sc);
        __half2 h1 = __floats2half2_rn(v.z * sc, v.w * sc);
        uint2 o;
        o.x = *reinterpret_cast<uint32_t*>(&h0);
        o.y = *reinterpret_cast<uint32_t*>(&h1);
        reinterpret_cast<uint2*>(g_yh)[i] = o;
    }
}

// ---------------- SpMM: aggh[r] = fp16( in_norm[r] * sum yh[colidx] ) ----------------
// one warp per dst row; lane owns 4 halves (8B); fp32 accumulation
__global__ __launch_bounds__(256) void k_spmm_h(int n) {
    int w = (blockIdx.x * blockDim.x + threadIdx.x) >> 5;
    int lane = threadIdx.x & 31;
    if (w >= n) return;
    int s = g_rowptr[w];
    int e = g_rowend[w];
    const uint2* __restrict__ yv = reinterpret_cast<const uint2*>(g_yh);
    float s0 = 0.f, s1 = 0.f, s2 = 0.f, s3 = 0.f;
    int i = s;
    for (; i + 4 <= e; i += 4) {
        int c0 = g_colidx[i], c1 = g_colidx[i + 1], c2 = g_colidx[i + 2], c3 = g_colidx[i + 3];
        uint2 u0 = yv[c0 * 32 + lane];
        uint2 u1 = yv[c1 * 32 + lane];
        uint2 u2 = yv[c2 * 32 + lane];
        uint2 u3 = yv[c3 * 32 + lane];
        #define ACCU(u) { \
            float2 f0 = __half22float2(*reinterpret_cast<__half2*>(&(u).x)); \
            float2 f1 = __half22float2(*reinterpret_cast<__half2*>(&(u).y)); \
            s0 += f0.x; s1 += f0.y; s2 += f1.x; s3 += f1.y; }
        ACCU(u0) ACCU(u1) ACCU(u2) ACCU(u3)
    }
    for (; i < e; i++) {
        uint2 u = yv[g_colidx[i] * 32 + lane];
        ACCU(u)
        #undef ACCU
    }
    float sc = g_innorm[w];
    __half2 h0 = __floats2half2_rn(s0 * sc, s1 * sc);
    __half2 h1 = __floats2half2_rn(s2 * sc, s3 * sc);
    uint2 o;
    o.x = *reinterpret_cast<uint32_t*>(&h0);
    o.y = *reinterpret_cast<uint32_t*>(&h1);
    reinterpret_cast<uint2*>(g_aggh)[w * 32 + lane] = o;
}

// ---------------- shared mma building blocks (WM=2, WN=4, MT=4 fixed) --------------
#define LDA 136
#define LDB 136

template <int NT>
__device__ __forceinline__ void mma_pass(const __half* As, const __half* Bs,
                                         int warpM, int warpN, int lane,
                                         float acc[4][NT][4]) {
    #pragma unroll
    for (int i = 0; i < 4; i++)
        #pragma unroll
        for (int j = 0; j < NT; j++)
            #pragma unroll
            for (int q = 0; q < 4; q++) acc[i][j][q] = 0.f;

    #pragma unroll
    for (int ks = 0; ks < 8; ks++) {
        int k0 = ks * 16;
        uint32_t af[4][4], bf[NT][2];
        #pragma unroll
        for (int i = 0; i < 4; i++) {
            const __half* p = As + (warpM * 64 + i * 16 + (lane & 15)) * LDA
                                 + k0 + ((lane >> 4) << 3);
            uint32_t sa = (uint32_t)__cvta_generic_to_shared(p);
            asm volatile("ldmatrix.sync.aligned.m8n8.x4.shared.b16 {%0,%1,%2,%3}, [%4];"
                         : "=r"(af[i][0]), "=r"(af[i][1]), "=r"(af[i][2]), "=r"(af[i][3])
                         : "r"(sa));
        }
        #pragma unroll
        for (int j = 0; j < NT; j++) {
            const __half* p = Bs + (k0 + (lane & 15)) * LDB + warpN * NT * 8 + j * 8;
            uint32_t sb = (uint32_t)__cvta_generic_to_shared(p);
            asm volatile("ldmatrix.sync.aligned.m8n8.x2.trans.shared.b16 {%0,%1}, [%2];"
                         : "=r"(bf[j][0]), "=r"(bf[j][1]) : "r"(sb));
        }
        #pragma unroll
        for (int i = 0; i < 4; i++)
            #pragma unroll
            for (int j = 0; j < NT; j++) {
                asm volatile(
                    "mma.sync.aligned.m16n8k16.row.col.f32.f16.f16.f32 "
                    "{%0,%1,%2,%3}, {%4,%5,%6,%7}, {%8,%9}, {%0,%1,%2,%3};\n"
                    : "+f"(acc[i][j][0]), "+f"(acc[i][j][1]),
                      "+f"(acc[i][j][2]), "+f"(acc[i][j][3])
                    : "r"(af[i][0]), "r"(af[i][1]), "r"(af[i][2]), "r"(af[i][3]),
                      "r"(bf[j][0]), "r"(bf[j][1]));
            }
    }
}

// relu(acc + bias) written back into the A smem tile (fp16) for the next pass
template <int NT>
__device__ __forceinline__ void epi_relu_to_smem(float acc[4][NT][4], const float* bias,
                                                 __half* As, int warpM, int warpN, int lane) {
    int g = lane >> 2, t = lane & 3;
    #pragma unroll
    for (int i = 0; i < 4; i++) {
        int rbase = warpM * 64 + i * 16 + g;
        #pragma unroll
        for (int j = 0; j < NT; j++) {
            int col = warpN * NT * 8 + j * 8 + 2 * t;
            float bv0 = bias[col], bv1 = bias[col + 1];
            #pragma unroll
            for (int hm = 0; hm < 2; hm++) {
                float v0 = fmaxf(acc[i][j][hm * 2 + 0] + bv0, 0.f);
                float v1 = fmaxf(acc[i][j][hm * 2 + 1] + bv1, 0.f);
                __half2 h = __floats2half2_rn(v0, v1);
                *reinterpret_cast<__half2*>(As + (rbase + hm * 8) * LDA + col) = h;
            }
        }
    }
}

__device__ __forceinline__ void load_b_tile(const __half* __restrict__ W, __half* Bs,
                                            int tid, int ncols8) {
    int nv = 128 * ncols8;
    for (int idx = tid; idx < nv; idx += 256) {
        int r = idx / ncols8, c = idx % ncols8;
        uint4 v = *reinterpret_cast<const uint4*>(W + (size_t)r * (ncols8 * 8) + c * 8);
        *reinterpret_cast<uint4*>(Bs + r * LDB + c * 8) = v;
    }
}

// ---------------- GEMM1: yh = fp16( relu(aggh@W1 + b1) * out_norm ) ----------------
__global__ __launch_bounds__(256) void k_gemm1(const float* __restrict__ bias, int M) {
    extern __shared__ __half sm[];
    __half* As = sm;
    __half* Bs = sm + 128 * LDA;
    int tid = threadIdx.x, lane = tid & 31, wid = tid >> 5;
    int warpM = wid & 1, warpN = wid >> 1;
    int rowBase = blockIdx.x * 128;

    for (int idx = tid; idx < 2048; idx += 256) {
        int r = idx >> 4, c = idx & 15;
        uint4 v = make_uint4(0u, 0u, 0u, 0u);
        if (rowBase + r < M)
            v = *reinterpret_cast<const uint4*>(g_aggh + (size_t)(rowBase + r) * 128 + c * 8);
        *reinterpret_cast<uint4*>(As + r * LDA + c * 8) = v;
    }
    load_b_tile(g_w1h, Bs, tid, 16);
    __syncthreads();

    float acc[4][4][4];
    mma_pass<4>(As, Bs, warpM, warpN, lane, acc);

    int g = lane >> 2, t = lane & 3;
    #pragma unroll
    for (int i = 0; i < 4; i++) {
        int rr = rowBase + warpM * 64 + i * 16 + g;
        #pragma unroll
        for (int j = 0; j < 4; j++) {
            int col = warpN * 32 + j * 8 + 2 * t;
            float bv0 = bias[col], bv1 = bias[col + 1];
            #pragma unroll
            for (int hm = 0; hm < 2; hm++) {
                int r = rr + hm * 8;
                if (r >= M) continue;
                float s = g_outnorm[r];
                float v0 = fmaxf(acc[i][j][hm * 2 + 0] + bv0, 0.f) * s;
                float v1 = fmaxf(acc[i][j][hm * 2 + 1] + bv1, 0.f) * s;
                __half2 h = __floats2half2_rn(v0, v1);
                *reinterpret_cast<__half2*>(g_yh + (size_t)r * 128 + col) = h;
            }
        }
    }
}

// ---------------- fused head: out = sigmoid(relu(relu(aggh@W2+b2)@Wm1+bm1)@Wm2+bm2) ----
__global__ __launch_bounds__(256) void k_fused_head(const float* __restrict__ b2,
                                                    const float* __restrict__ bm1,
                                                    const float* __restrict__ bm2,
                                                    float* __restrict__ out, int M) {
    extern __shared__ __half sm[];
    __half* As = sm;
    __half* Bs = sm + 128 * LDA;
    int tid = threadIdx.x, lane = tid & 31, wid = tid >> 5;
    int warpM = wid & 1, warpN = wid >> 1;
    int rowBase = blockIdx.x * 128;

    // A = agg2 tile (zeros beyond M keep all stages defined)
    for (int idx = tid; idx < 2048; idx += 256) {
        int r = idx >> 4, c = idx & 15;
        uint4 v = make_uint4(0u, 0u, 0u, 0u);
        if (rowBase + r < M)
            v = *reinterpret_cast<const uint4*>(g_aggh + (size_t)(rowBase + r) * 128 + c * 8);
        *reinterpret_cast<uint4*>(As + r * LDA + c * 8) = v;
    }
    load_b_tile(g_w2h, Bs, tid, 16);
    __syncthreads();

    float acc[4][4][4];

    // stage 1: h2 = relu(A@W2 + b2) -> As
    mma_pass<4>(As, Bs, warpM, warpN, lane, acc);
    __syncthreads();                       // all ldmatrix reads of As done
    epi_relu_to_smem<4>(acc, b2, As, warpM, warpN, lane);
    load_b_tile(g_wm1h, Bs, tid, 16);      // Bs readers also done (same sync)
    __syncthreads();

    // stage 2: m1 = relu(h2@Wm1 + bm1) -> As
    mma_pass<4>(As, Bs, warpM, warpN, lane, acc);
    __syncthreads();
    epi_relu_to_smem<4>(acc, bm1, As, warpM, warpN, lane);
    load_b_tile(g_wm2h, Bs, tid, 8);       // 128 x 64
    __syncthreads();

    // stage 3: out = sigmoid(m1@Wm2 + bm2) -> global fp32 [M,64]
    float acc2[4][2][4];
    mma_pass<2>(As, Bs, warpM, warpN, lane, acc2);

    int g = lane >> 2, t = lane & 3;
    #pragma unroll
    for (int i = 0; i < 4; i++) {
        int rr = rowBase + warpM * 64 + i * 16 + g;
        #pragma unroll
        for (int j = 0; j < 2; j++) {
            int col = warpN * 16 + j * 8 + 2 * t;
            float bv0 = bm2[col], bv1 = bm2[col + 1];
            #pragma unroll
            for (int hm = 0; hm < 2; hm++) {
                int r = rr + hm * 8;
                if (r >= M) continue;
                float v0 = acc2[i][j][hm * 2 + 0] + bv0;
                float v1 = acc2[i][j][hm * 2 + 1] + bv1;
                float2 o;
                o.x = 1.f / (1.f + __expf(-v0));
                o.y = 1.f / (1.f + __expf(-v1));
                *reinterpret_cast<float2*>(out + (size_t)r * 64 + col) = o;
            }
        }
    }
}

// ---------------- launch ----------------
extern "C" void kernel_launch(void* const* d_in, const int* in_sizes, int n_in,
                              void* d_out, int out_size) {
    const float* x   = (const float*)d_in[0];
    const int*   src = (const int*)d_in[1];
    const int*   dst = (const int*)d_in[2];
    const float* W1  = (const float*)d_in[3];
    const float* b1  = (const float*)d_in[4];
    const float* W2  = (const float*)d_in[5];
    const float* b2  = (const float*)d_in[6];
    const float* Wm1 = (const float*)d_in[7];
    const float* bm1 = (const float*)d_in[8];
    const float* Wm2 = (const float*)d_in[9];
    const float* bm2 = (const float*)d_in[10];
    float* out = (float*)d_out;

    int n = in_sizes[0] / F;     // 100000
    int e = in_sizes[1];         // 3200000

    const int SMEM = 2 * 128 * LDA * 2;   // 69632 bytes
    cudaFuncSetAttribute(k_gemm1, cudaFuncAttributeMaxDynamicSharedMemorySize, SMEM);
    cudaFuncSetAttribute(k_fused_head, cudaFuncAttributeMaxDynamicSharedMemorySize, SMEM);

    int nbN = (n + 255) / 256;
    int nbE = (e + 255) / 256;
    int nbW = (n * 32 + 255) / 256;
    int nbV = (n * F4 + 255) / 256;
    int nbG = (n + 127) / 128;

    // graph preprocessing (CSR by dst + norms)
    k_zero<<<nbN, 256>>>(n);
    k_count<<<nbE, 256>>>(src, dst, e);
    k_scan_norm<<<nbN, 256>>>(n);
    k_fill<<<nbE, 256>>>(src, dst, e);

    // weights -> fp16 (one launch)
    k_f2h_all<<<(57344 + 255) / 256, 256>>>(W1, W2, Wm1, Wm2);

    // conv1
    k_scale_h<<<nbV, 256>>>(x, n);                 // yh = fp16(x * out_norm)
    k_spmm_h<<<nbW, 256>>>(n);                     // aggh = fp16(in_norm * S yh)
    k_gemm1<<<nbG, 256, SMEM>>>(b1, n);            // yh = fp16(relu(.)@W1 * out_norm)

    // conv2 + MLP head (fully fused tail)
    k_spmm_h<<<nbW, 256>>>(n);                     // aggh = fp16(in_norm * S yh)
    k_fused_head<<<nbG, 256, SMEM>>>(b2, bm1, bm2, out, n);
}